// round 11
// baseline (speedup 1.0000x reference)
#include <cuda_runtime.h>
#include <cuda_bf16.h>
#include <cstdint>

// Problem constants (fixed by the dataset)
#define N_NODES_MAX 50048
#define N_EDGES_MAX 800000
#define IN_FEATS    128
#define NUM_HEADS   4
#define OUT_FEATS   32
#define HD          (NUM_HEADS * OUT_FEATS)   // 128

#define SCAN_B 1024
#define MAX_BLOCKS ((N_NODES_MAX + SCAN_B - 1) / SCAN_B + 2)

// Scratch (static __device__ arrays; no allocation allowed)
__device__ float g_ft[N_NODES_MAX * HD];     // projected features [N,128]
__device__ int   g_cnt[N_NODES_MAX];         // in-degree histogram
__device__ int   g_off[N_NODES_MAX];         // CSR row starts
__device__ int   g_cur[N_NODES_MAX];         // scatter cursors
__device__ int   g_bsum[MAX_BLOCKS];         // per-block sums for scan
__device__ int   g_csr_src[N_EDGES_MAX];     // src node per CSR slot

// ---------------------------------------------------------------------------
// K1: in-degree histogram
// ---------------------------------------------------------------------------
__global__ void hist_kernel(const int* __restrict__ dst, int E) {
    int i = blockIdx.x * blockDim.x + threadIdx.x;
    if (i < E) atomicAdd(&g_cnt[dst[i]], 1);
}

// ---------------------------------------------------------------------------
// K2a: per-block sums for the scan
// ---------------------------------------------------------------------------
__global__ void scan_phase1(int N) {
    int i = blockIdx.x * SCAN_B + threadIdx.x;
    int v = (i < N) ? g_cnt[i] : 0;
    #pragma unroll
    for (int o = 16; o > 0; o >>= 1) v += __shfl_xor_sync(0xffffffffu, v, o);
    __shared__ int wsum[32];
    int lane = threadIdx.x & 31, w = threadIdx.x >> 5;
    if (lane == 0) wsum[w] = v;
    __syncthreads();
    if (w == 0) {
        int x = wsum[lane];
        #pragma unroll
        for (int o = 16; o > 0; o >>= 1) x += __shfl_xor_sync(0xffffffffu, x, o);
        if (lane == 0) g_bsum[blockIdx.x] = x;
    }
}

// ---------------------------------------------------------------------------
// K2b: per-block scan with inter-block base folded in (warp 0 sums g_bsum).
// ---------------------------------------------------------------------------
__global__ void scan_phase3(int N) {
    __shared__ int base_off;
    int lane = threadIdx.x & 31, w = threadIdx.x >> 5;
    if (threadIdx.x < 32) {
        int acc = 0;
        for (int j = lane; j < (int)blockIdx.x; j += 32) acc += g_bsum[j];
        #pragma unroll
        for (int o = 16; o > 0; o >>= 1) acc += __shfl_xor_sync(0xffffffffu, acc, o);
        if (lane == 0) base_off = acc;
    }
    int i = blockIdx.x * SCAN_B + threadIdx.x;
    int v = (i < N) ? g_cnt[i] : 0;
    int x = v;
    #pragma unroll
    for (int o = 1; o < 32; o <<= 1) {
        int y = __shfl_up_sync(0xffffffffu, x, o);
        if (lane >= o) x += y;
    }
    __shared__ int woff[32];
    if (lane == 31) woff[w] = x;
    __syncthreads();
    if (w == 0) {
        int y = woff[lane];
        int z = y;
        #pragma unroll
        for (int o = 1; o < 32; o <<= 1) {
            int t2 = __shfl_up_sync(0xffffffffu, z, o);
            if (lane >= o) z += t2;
        }
        woff[lane] = z - y;
    }
    __syncthreads();
    int excl = (x - v) + woff[w] + base_off;
    if (i < N) { g_off[i] = excl; g_cur[i] = excl; }
}

// ---------------------------------------------------------------------------
// K3: scatter src ids into CSR slots
// ---------------------------------------------------------------------------
__global__ void scatter_kernel(const int* __restrict__ src,
                               const int* __restrict__ dst, int E) {
    int i = blockIdx.x * blockDim.x + threadIdx.x;
    if (i < E) {
        int pos = atomicAdd(&g_cur[dst[i]], 1);
        g_csr_src[pos] = src[i];
    }
}

// ---------------------------------------------------------------------------
// K4: projection GEMM, single-wave shape. ft[n][o] = sum_k feat[n][k]*W[o][k].
// 128x128 tile, BK=16, 512 threads, 4x8 microtile (32 acc regs as 16 u64).
// __launch_bounds__(512,3): 3 CTAs/SM -> 444-CTA wave >= 391 CTAs = ONE wave
// (the old 256-thread/occ-2 shape ran 1.32 waves; the straggler wave cost
// ~50% extra). 48 resident warps/SM hide LDS + sync latency.
// FFMA2 inner loop; register-staged prefetch of k-block t+1 over compute of t.
// Runs on a forked stream, concurrent with the CSR build.
// ---------------------------------------------------------------------------
#define GM 128
#define GK 16
__global__ void __launch_bounds__(512, 3)
gemm_kernel(const float* __restrict__ feat,
            const float* __restrict__ W,
            int N) {
    __shared__ float As[GK][GM];    // feat tile, transposed: As[k][r]   8KB
    __shared__ float Bs[GK][HD];    // W tile, transposed:    Bs[k][o]   8KB

    const int tid = threadIdx.x;           // 0..511
    const int tx  = tid & 15;              // col group: cols tx*8..tx*8+7
    const int ty  = tid >> 4;              // row group 0..31: rows ty*4..ty*4+3
    const int row0 = blockIdx.x * GM;

    // Staging indices: 512 float4 loads cover a 128x16 tile; 1 per thread.
    const int rA = tid >> 2, kq = tid & 3;

    unsigned long long acc[4][4];   // 4 rows x 4 f32x2 pairs (= 8 cols)
    #pragma unroll
    for (int i = 0; i < 4; i++)
        #pragma unroll
        for (int j = 0; j < 4; j++) acc[i][j] = 0ULL;

    // Prologue: stage k-block 0 into registers
    float4 fa, fw;
    {
        fa = make_float4(0.f, 0.f, 0.f, 0.f);
        if (row0 + rA < N) fa = *(const float4*)&feat[(size_t)(row0 + rA) * IN_FEATS + (kq << 2)];
        fw = *(const float4*)&W[(size_t)rA * IN_FEATS + (kq << 2)];
    }

    #pragma unroll 1
    for (int kb = 0; kb < IN_FEATS / GK; kb++) {
        As[(kq << 2) + 0][rA] = fa.x; As[(kq << 2) + 1][rA] = fa.y;
        As[(kq << 2) + 2][rA] = fa.z; As[(kq << 2) + 3][rA] = fa.w;
        Bs[(kq << 2) + 0][rA] = fw.x; Bs[(kq << 2) + 1][rA] = fw.y;
        Bs[(kq << 2) + 2][rA] = fw.z; Bs[(kq << 2) + 3][rA] = fw.w;
        __syncthreads();

        // Stage next k-block (LDG latency overlaps the FFMA2 block below)
        if (kb + 1 < IN_FEATS / GK) {
            int kc = (kb + 1) * GK;
            fa = make_float4(0.f, 0.f, 0.f, 0.f);
            if (row0 + rA < N) fa = *(const float4*)&feat[(size_t)(row0 + rA) * IN_FEATS + kc + (kq << 2)];
            fw = *(const float4*)&W[(size_t)rA * IN_FEATS + kc + (kq << 2)];
        }

        #pragma unroll
        for (int k = 0; k < GK; k++) {
            float4 a0 = *(const float4*)&As[k][(ty << 2)];
            float4 b0 = *(const float4*)&Bs[k][(tx << 3) + 0];
            float4 b1 = *(const float4*)&Bs[k][(tx << 3) + 4];
            unsigned long long bp[4];
            asm("mov.b64 %0, {%1, %2};" : "=l"(bp[0]) : "f"(b0.x), "f"(b0.y));
            asm("mov.b64 %0, {%1, %2};" : "=l"(bp[1]) : "f"(b0.z), "f"(b0.w));
            asm("mov.b64 %0, {%1, %2};" : "=l"(bp[2]) : "f"(b1.x), "f"(b1.y));
            asm("mov.b64 %0, {%1, %2};" : "=l"(bp[3]) : "f"(b1.z), "f"(b1.w));
            float av[4] = {a0.x, a0.y, a0.z, a0.w};
            #pragma unroll
            for (int i = 0; i < 4; i++) {
                unsigned long long ap;
                asm("mov.b64 %0, {%1, %1};" : "=l"(ap) : "f"(av[i]));
                #pragma unroll
                for (int jp = 0; jp < 4; jp++)
                    asm("fma.rn.f32x2 %0, %1, %2, %0;"
                        : "+l"(acc[i][jp]) : "l"(ap), "l"(bp[jp]));
            }
        }
        __syncthreads();
    }

    // Epilogue: each row's 4 u64 pairs == 8 contiguous floats; two STG.128.
    #pragma unroll
    for (int i = 0; i < 4; i++) {
        int r = row0 + (ty << 2) + i;
        if (r < N) {
            unsigned long long* d =
                (unsigned long long*)&g_ft[(size_t)r * HD + (tx << 3)];
            ulonglong2 v0; v0.x = acc[i][0]; v0.y = acc[i][1];
            ulonglong2 v1; v1.x = acc[i][2]; v1.y = acc[i][3];
            *(ulonglong2*)(d + 0) = v0;
            *(ulonglong2*)(d + 2) = v1;
        }
    }
}

// ---------------------------------------------------------------------------
// K5: atomic-free aggregation — R8 version EXACTLY (measured best; depth-2
// prefetch regressed +9us in R10, do not reintroduce).
// One warp per DST node, depth-1 software pipeline, unroll 2.
// Max-subtraction skipped: mathematically identical softmax; |p*scale| <~ 7.
// ---------------------------------------------------------------------------
__global__ void agg_kernel(float* __restrict__ out, int N) {
    const int node = (blockIdx.x * blockDim.x + threadIdx.x) >> 5;
    if (node >= N) return;
    const int lane = threadIdx.x & 31;

    const int start = g_off[node];
    const int deg   = g_cnt[node];

    const float4* ft4 = (const float4*)g_ft;
    const float4 b4 = ft4[(size_t)node * 32 + lane];

    float4 acc = make_float4(0.f, 0.f, 0.f, 0.f);
    float s = 0.0f;
    const float scale = 0.17677669529663687f;  // 1/sqrt(32)

    for (int base = 0; base < deg; base += 32) {
        int j = base + lane;
        int sj = (j < deg) ? g_csr_src[start + j] : 0;
        int cnt = min(32, deg - base);

        int sn0 = __shfl_sync(0xffffffffu, sj, 0);
        float4 a4 = ft4[(size_t)sn0 * 32 + lane];

        #pragma unroll 2
        for (int t = 0; t < cnt; t++) {
            float4 cur = a4;
            if (t + 1 < cnt) {   // prefetch next edge's row
                int sn = __shfl_sync(0xffffffffu, sj, t + 1);
                a4 = ft4[(size_t)sn * 32 + lane];
            }
            float p = cur.x * b4.x + cur.y * b4.y + cur.z * b4.z + cur.w * b4.w;
            p += __shfl_xor_sync(0xffffffffu, p, 4);
            p += __shfl_xor_sync(0xffffffffu, p, 2);
            p += __shfl_xor_sync(0xffffffffu, p, 1);
            float e = __expf(p * scale);
            s += e;
            acc.x += e * cur.x; acc.y += e * cur.y;
            acc.z += e * cur.z; acc.w += e * cur.w;
        }
    }

    float inv = (deg > 0) ? (1.0f / s) : 0.0f;
    float4 r = make_float4(acc.x * inv, acc.y * inv, acc.z * inv, acc.w * inv);
    ((float4*)out)[(size_t)node * 32 + lane] = r;
}

// ---------------------------------------------------------------------------
extern "C" void kernel_launch(void* const* d_in, const int* in_sizes, int n_in,
                              void* d_out, int out_size) {
    const float* feat = (const float*)d_in[0];
    const float* W    = (const float*)d_in[1];
    const int*   src  = (const int*)d_in[2];
    const int*   dst  = (const int*)d_in[3];
    float* out = (float*)d_out;

    const int N = in_sizes[0] / IN_FEATS;   // 50000
    const int E = in_sizes[2];              // 800000
    const int nb = (N + SCAN_B - 1) / SCAN_B;

    // One-time resources (stream/events/symbol addr) — resources only;
    // the captured work per call is identical every time.
    static cudaStream_t s_gemm = nullptr;
    static cudaEvent_t  ev_fork = nullptr, ev_join = nullptr;
    static int* cnt_ptr = nullptr;
    if (s_gemm == nullptr) {
        cudaStreamCreateWithFlags(&s_gemm, cudaStreamNonBlocking);
        cudaEventCreateWithFlags(&ev_fork, cudaEventDisableTiming);
        cudaEventCreateWithFlags(&ev_join, cudaEventDisableTiming);
        cudaGetSymbolAddress((void**)&cnt_ptr, g_cnt);
    }

    // ---- fork: GEMM branch issued FIRST (R8 order — measured best) ----
    cudaEventRecord(ev_fork, 0);
    cudaStreamWaitEvent(s_gemm, ev_fork, 0);
    gemm_kernel<<<(N + GM - 1) / GM, 512, 0, s_gemm>>>(feat, W, N);
    cudaEventRecord(ev_join, s_gemm);

    // ---- main stream: CSR build branch (depends only on src, dst) ----
    cudaMemsetAsync(cnt_ptr, 0, (size_t)N * sizeof(int));
    hist_kernel<<<(E + 255) / 256, 256>>>(dst, E);
    scan_phase1<<<nb, SCAN_B>>>(N);
    scan_phase3<<<nb, SCAN_B>>>(N);
    scatter_kernel<<<(E + 255) / 256, 256>>>(src, dst, E);

    // ---- join, then aggregate ----
    cudaStreamWaitEvent(0, ev_join, 0);
    {
        int warps_per_block = 8;  // 256 threads
        int blocks = (N + warps_per_block - 1) / warps_per_block;
        agg_kernel<<<blocks, 256>>>(out, N);
    }
}

// round 12
// speedup vs baseline: 1.1733x; 1.1733x over previous
#include <cuda_runtime.h>
#include <cuda_bf16.h>
#include <cstdint>

// Problem constants (fixed by the dataset)
#define N_NODES_MAX 50048
#define N_EDGES_MAX 800000
#define IN_FEATS    128
#define NUM_HEADS   4
#define OUT_FEATS   32
#define HD          (NUM_HEADS * OUT_FEATS)   // 128

#define SCAN_B 1024
#define MAX_BLOCKS ((N_NODES_MAX + SCAN_B - 1) / SCAN_B + 2)

// Scratch (static __device__ arrays; no allocation allowed)
// g_cnt is zero-initialized at module load and re-zeroed by agg_kernel at the
// end of every call, so hist_kernel never needs a memset.
__device__ float g_ft[N_NODES_MAX * HD];     // projected features [N,128]
__device__ int   g_cnt[N_NODES_MAX];         // in-degree histogram
__device__ int   g_off[N_NODES_MAX];         // CSR row starts
__device__ int   g_cur[N_NODES_MAX];         // scatter cursors
__device__ int   g_bsum[MAX_BLOCKS];         // per-block sums for scan
__device__ int   g_csr_src[N_EDGES_MAX];     // src node per CSR slot

// ---------------------------------------------------------------------------
// K1: in-degree histogram (g_cnt arrives zeroed — see agg_kernel epilogue)
// ---------------------------------------------------------------------------
__global__ void hist_kernel(const int* __restrict__ dst, int E) {
    int i = blockIdx.x * blockDim.x + threadIdx.x;
    if (i < E) atomicAdd(&g_cnt[dst[i]], 1);
}

// ---------------------------------------------------------------------------
// K2a: per-block sums for the scan
// ---------------------------------------------------------------------------
__global__ void scan_phase1(int N) {
    int i = blockIdx.x * SCAN_B + threadIdx.x;
    int v = (i < N) ? g_cnt[i] : 0;
    #pragma unroll
    for (int o = 16; o > 0; o >>= 1) v += __shfl_xor_sync(0xffffffffu, v, o);
    __shared__ int wsum[32];
    int lane = threadIdx.x & 31, w = threadIdx.x >> 5;
    if (lane == 0) wsum[w] = v;
    __syncthreads();
    if (w == 0) {
        int x = wsum[lane];
        #pragma unroll
        for (int o = 16; o > 0; o >>= 1) x += __shfl_xor_sync(0xffffffffu, x, o);
        if (lane == 0) g_bsum[blockIdx.x] = x;
    }
}

// ---------------------------------------------------------------------------
// K2b: per-block scan with inter-block base folded in (warp 0 sums g_bsum).
// ---------------------------------------------------------------------------
__global__ void scan_phase3(int N) {
    __shared__ int base_off;
    int lane = threadIdx.x & 31, w = threadIdx.x >> 5;
    if (threadIdx.x < 32) {
        int acc = 0;
        for (int j = lane; j < (int)blockIdx.x; j += 32) acc += g_bsum[j];
        #pragma unroll
        for (int o = 16; o > 0; o >>= 1) acc += __shfl_xor_sync(0xffffffffu, acc, o);
        if (lane == 0) base_off = acc;
    }
    int i = blockIdx.x * SCAN_B + threadIdx.x;
    int v = (i < N) ? g_cnt[i] : 0;
    int x = v;
    #pragma unroll
    for (int o = 1; o < 32; o <<= 1) {
        int y = __shfl_up_sync(0xffffffffu, x, o);
        if (lane >= o) x += y;
    }
    __shared__ int woff[32];
    if (lane == 31) woff[w] = x;
    __syncthreads();
    if (w == 0) {
        int y = woff[lane];
        int z = y;
        #pragma unroll
        for (int o = 1; o < 32; o <<= 1) {
            int t2 = __shfl_up_sync(0xffffffffu, z, o);
            if (lane >= o) z += t2;
        }
        woff[lane] = z - y;
    }
    __syncthreads();
    int excl = (x - v) + woff[w] + base_off;
    if (i < N) { g_off[i] = excl; g_cur[i] = excl; }
}

// ---------------------------------------------------------------------------
// K3: scatter src ids into CSR slots
// ---------------------------------------------------------------------------
__global__ void scatter_kernel(const int* __restrict__ src,
                               const int* __restrict__ dst, int E) {
    int i = blockIdx.x * blockDim.x + threadIdx.x;
    if (i < E) {
        int pos = atomicAdd(&g_cur[dst[i]], 1);
        g_csr_src[pos] = src[i];
    }
}

// ---------------------------------------------------------------------------
// K4: projection GEMM — single-wave shape, same bytes/MAC as R8's best.
// GM=64 x BN=128 tile, BK=16, 128 threads, 8x8 microtile (FFMA2 pairs).
// Crossbar traffic identical to the 128x128/256t shape (64 B/thread/k),
// but 782 CTAs at occupancy 5 (740-CTA wave) = 1.06 waves instead of 1.32->2:
// the straggler wave shrinks from 50% to 6%.
// Register-staged prefetch of k-block t+1 over compute of t.
// Runs on a forked stream, concurrent with the CSR build.
// ---------------------------------------------------------------------------
#define GM 64
#define GK 16
__global__ void __launch_bounds__(128, 5)
gemm_kernel(const float* __restrict__ feat,
            const float* __restrict__ W,
            int N) {
    __shared__ float As[GK][GM];    // feat tile, transposed: As[k][r]   4KB
    __shared__ float Bs[GK][HD];    // W tile, transposed:    Bs[k][o]   8KB

    const int tid = threadIdx.x;           // 0..127
    const int tx  = tid & 15;              // col group: cols tx*8..tx*8+7
    const int ty  = tid >> 4;              // row group 0..7: rows ty*8..ty*8+7
    const int row0 = blockIdx.x * GM;

    // A staging: 64x16 tile = 256 float4 -> 2 per thread.
    const int rA0 = (tid + 0)   >> 2, kqA0 = (tid + 0)   & 3;
    const int rA1 = (tid + 128) >> 2, kqA1 = (tid + 128) & 3;
    // W staging: 128x16 tile = 512 float4 -> 4 per thread.
    const int rW0 = (tid + 0)   >> 2, kqW0 = (tid + 0)   & 3;
    const int rW1 = (tid + 128) >> 2, kqW1 = (tid + 128) & 3;
    const int rW2 = (tid + 256) >> 2, kqW2 = (tid + 256) & 3;
    const int rW3 = (tid + 384) >> 2, kqW3 = (tid + 384) & 3;

    unsigned long long acc[8][4];   // 8 rows x 4 f32x2 pairs (= 8 cols)
    #pragma unroll
    for (int i = 0; i < 8; i++)
        #pragma unroll
        for (int j = 0; j < 4; j++) acc[i][j] = 0ULL;

    // Prologue: stage k-block 0 into registers
    float4 fa0, fa1, fw0, fw1, fw2, fw3;
    {
        fa0 = make_float4(0.f, 0.f, 0.f, 0.f);
        fa1 = fa0;
        if (row0 + rA0 < N) fa0 = *(const float4*)&feat[(size_t)(row0 + rA0) * IN_FEATS + (kqA0 << 2)];
        if (row0 + rA1 < N) fa1 = *(const float4*)&feat[(size_t)(row0 + rA1) * IN_FEATS + (kqA1 << 2)];
        fw0 = *(const float4*)&W[(size_t)rW0 * IN_FEATS + (kqW0 << 2)];
        fw1 = *(const float4*)&W[(size_t)rW1 * IN_FEATS + (kqW1 << 2)];
        fw2 = *(const float4*)&W[(size_t)rW2 * IN_FEATS + (kqW2 << 2)];
        fw3 = *(const float4*)&W[(size_t)rW3 * IN_FEATS + (kqW3 << 2)];
    }

    #pragma unroll 1
    for (int kb = 0; kb < IN_FEATS / GK; kb++) {
        As[(kqA0 << 2) + 0][rA0] = fa0.x; As[(kqA0 << 2) + 1][rA0] = fa0.y;
        As[(kqA0 << 2) + 2][rA0] = fa0.z; As[(kqA0 << 2) + 3][rA0] = fa0.w;
        As[(kqA1 << 2) + 0][rA1] = fa1.x; As[(kqA1 << 2) + 1][rA1] = fa1.y;
        As[(kqA1 << 2) + 2][rA1] = fa1.z; As[(kqA1 << 2) + 3][rA1] = fa1.w;
        Bs[(kqW0 << 2) + 0][rW0] = fw0.x; Bs[(kqW0 << 2) + 1][rW0] = fw0.y;
        Bs[(kqW0 << 2) + 2][rW0] = fw0.z; Bs[(kqW0 << 2) + 3][rW0] = fw0.w;
        Bs[(kqW1 << 2) + 0][rW1] = fw1.x; Bs[(kqW1 << 2) + 1][rW1] = fw1.y;
        Bs[(kqW1 << 2) + 2][rW1] = fw1.z; Bs[(kqW1 << 2) + 3][rW1] = fw1.w;
        Bs[(kqW2 << 2) + 0][rW2] = fw2.x; Bs[(kqW2 << 2) + 1][rW2] = fw2.y;
        Bs[(kqW2 << 2) + 2][rW2] = fw2.z; Bs[(kqW2 << 2) + 3][rW2] = fw2.w;
        Bs[(kqW3 << 2) + 0][rW3] = fw3.x; Bs[(kqW3 << 2) + 1][rW3] = fw3.y;
        Bs[(kqW3 << 2) + 2][rW3] = fw3.z; Bs[(kqW3 << 2) + 3][rW3] = fw3.w;
        __syncthreads();

        // Stage next k-block (LDG latency overlaps the FFMA2 block below)
        if (kb + 1 < IN_FEATS / GK) {
            int kc = (kb + 1) * GK;
            fa0 = make_float4(0.f, 0.f, 0.f, 0.f);
            fa1 = fa0;
            if (row0 + rA0 < N) fa0 = *(const float4*)&feat[(size_t)(row0 + rA0) * IN_FEATS + kc + (kqA0 << 2)];
            if (row0 + rA1 < N) fa1 = *(const float4*)&feat[(size_t)(row0 + rA1) * IN_FEATS + kc + (kqA1 << 2)];
            fw0 = *(const float4*)&W[(size_t)rW0 * IN_FEATS + kc + (kqW0 << 2)];
            fw1 = *(const float4*)&W[(size_t)rW1 * IN_FEATS + kc + (kqW1 << 2)];
            fw2 = *(const float4*)&W[(size_t)rW2 * IN_FEATS + kc + (kqW2 << 2)];
            fw3 = *(const float4*)&W[(size_t)rW3 * IN_FEATS + kc + (kqW3 << 2)];
        }

        #pragma unroll
        for (int k = 0; k < GK; k++) {
            float4 a0 = *(const float4*)&As[k][(ty << 3) + 0];
            float4 a1 = *(const float4*)&As[k][(ty << 3) + 4];
            float4 b0 = *(const float4*)&Bs[k][(tx << 3) + 0];
            float4 b1 = *(const float4*)&Bs[k][(tx << 3) + 4];
            unsigned long long bp[4];
            asm("mov.b64 %0, {%1, %2};" : "=l"(bp[0]) : "f"(b0.x), "f"(b0.y));
            asm("mov.b64 %0, {%1, %2};" : "=l"(bp[1]) : "f"(b0.z), "f"(b0.w));
            asm("mov.b64 %0, {%1, %2};" : "=l"(bp[2]) : "f"(b1.x), "f"(b1.y));
            asm("mov.b64 %0, {%1, %2};" : "=l"(bp[3]) : "f"(b1.z), "f"(b1.w));
            float av[8] = {a0.x, a0.y, a0.z, a0.w, a1.x, a1.y, a1.z, a1.w};
            #pragma unroll
            for (int i = 0; i < 8; i++) {
                unsigned long long ap;
                asm("mov.b64 %0, {%1, %1};" : "=l"(ap) : "f"(av[i]));
                #pragma unroll
                for (int jp = 0; jp < 4; jp++)
                    asm("fma.rn.f32x2 %0, %1, %2, %0;"
                        : "+l"(acc[i][jp]) : "l"(ap), "l"(bp[jp]));
            }
        }
        __syncthreads();
    }

    // Epilogue: each row's 4 u64 pairs == 8 contiguous floats; two STG.128.
    #pragma unroll
    for (int i = 0; i < 8; i++) {
        int r = row0 + (ty << 3) + i;
        if (r < N) {
            unsigned long long* d =
                (unsigned long long*)&g_ft[(size_t)r * HD + (tx << 3)];
            ulonglong2 v0; v0.x = acc[i][0]; v0.y = acc[i][1];
            ulonglong2 v1; v1.x = acc[i][2]; v1.y = acc[i][3];
            *(ulonglong2*)(d + 0) = v0;
            *(ulonglong2*)(d + 2) = v1;
        }
    }
}

// ---------------------------------------------------------------------------
// K5: atomic-free aggregation — R8 version (measured best; depth-2 prefetch
// regressed +9us in R10, do not reintroduce). One warp per DST node,
// depth-1 software pipeline, unroll 2. Epilogue re-zeros g_cnt so the next
// replay's hist_kernel needs no memset.
// Max-subtraction skipped: mathematically identical softmax; |p*scale| <~ 7.
// ---------------------------------------------------------------------------
__global__ void agg_kernel(float* __restrict__ out, int N) {
    const int node = (blockIdx.x * blockDim.x + threadIdx.x) >> 5;
    if (node >= N) return;
    const int lane = threadIdx.x & 31;

    const int start = g_off[node];
    const int deg   = g_cnt[node];
    if (lane == 0) g_cnt[node] = 0;   // re-arm histogram for the next replay

    const float4* ft4 = (const float4*)g_ft;
    const float4 b4 = ft4[(size_t)node * 32 + lane];

    float4 acc = make_float4(0.f, 0.f, 0.f, 0.f);
    float s = 0.0f;
    const float scale = 0.17677669529663687f;  // 1/sqrt(32)

    for (int base = 0; base < deg; base += 32) {
        int j = base + lane;
        int sj = (j < deg) ? g_csr_src[start + j] : 0;
        int cnt = min(32, deg - base);

        int sn0 = __shfl_sync(0xffffffffu, sj, 0);
        float4 a4 = ft4[(size_t)sn0 * 32 + lane];

        #pragma unroll 2
        for (int t = 0; t < cnt; t++) {
            float4 cur = a4;
            if (t + 1 < cnt) {   // prefetch next edge's row
                int sn = __shfl_sync(0xffffffffu, sj, t + 1);
                a4 = ft4[(size_t)sn * 32 + lane];
            }
            float p = cur.x * b4.x + cur.y * b4.y + cur.z * b4.z + cur.w * b4.w;
            p += __shfl_xor_sync(0xffffffffu, p, 4);
            p += __shfl_xor_sync(0xffffffffu, p, 2);
            p += __shfl_xor_sync(0xffffffffu, p, 1);
            float e = __expf(p * scale);
            s += e;
            acc.x += e * cur.x; acc.y += e * cur.y;
            acc.z += e * cur.z; acc.w += e * cur.w;
        }
    }

    float inv = (deg > 0) ? (1.0f / s) : 0.0f;
    float4 r = make_float4(acc.x * inv, acc.y * inv, acc.z * inv, acc.w * inv);
    ((float4*)out)[(size_t)node * 32 + lane] = r;
}

// ---------------------------------------------------------------------------
extern "C" void kernel_launch(void* const* d_in, const int* in_sizes, int n_in,
                              void* d_out, int out_size) {
    const float* feat = (const float*)d_in[0];
    const float* W    = (const float*)d_in[1];
    const int*   src  = (const int*)d_in[2];
    const int*   dst  = (const int*)d_in[3];
    float* out = (float*)d_out;

    const int N = in_sizes[0] / IN_FEATS;   // 50000
    const int E = in_sizes[2];              // 800000
    const int nb = (N + SCAN_B - 1) / SCAN_B;

    // One-time resources (stream/events) — resources only; the captured work
    // per call is identical every time.
    static cudaStream_t s_gemm = nullptr;
    static cudaEvent_t  ev_fork = nullptr, ev_join = nullptr;
    if (s_gemm == nullptr) {
        cudaStreamCreateWithFlags(&s_gemm, cudaStreamNonBlocking);
        cudaEventCreateWithFlags(&ev_fork, cudaEventDisableTiming);
        cudaEventCreateWithFlags(&ev_join, cudaEventDisableTiming);
    }

    // ---- fork: GEMM branch issued FIRST (R8 order — measured best) ----
    cudaEventRecord(ev_fork, 0);
    cudaStreamWaitEvent(s_gemm, ev_fork, 0);
    gemm_kernel<<<(N + GM - 1) / GM, 128, 0, s_gemm>>>(feat, W, N);
    cudaEventRecord(ev_join, s_gemm);

    // ---- main stream: CSR build branch (depends only on src, dst) ----
    hist_kernel<<<(E + 255) / 256, 256>>>(dst, E);
    scan_phase1<<<nb, SCAN_B>>>(N);
    scan_phase3<<<nb, SCAN_B>>>(N);
    scatter_kernel<<<(E + 255) / 256, 256>>>(src, dst, E);

    // ---- join, then aggregate ----
    cudaStreamWaitEvent(0, ev_join, 0);
    {
        int warps_per_block = 8;  // 256 threads
        int blocks = (N + warps_per_block - 1) / warps_per_block;
        agg_kernel<<<blocks, 256>>>(out, N);
    }
}

// round 13
// speedup vs baseline: 1.9316x; 1.6463x over previous
#include <cuda_runtime.h>
#include <cuda_fp16.h>
#include <cuda_bf16.h>
#include <cstdint>

// Problem constants (fixed by the dataset)
#define N_NODES_MAX 50048
#define N_EDGES_MAX 800000
#define IN_FEATS    128
#define NUM_HEADS   4
#define OUT_FEATS   32
#define HD          (NUM_HEADS * OUT_FEATS)   // 128

#define SCAN_B 1024
#define MAX_BLOCKS ((N_NODES_MAX + SCAN_B - 1) / SCAN_B + 2)

// Scratch (static __device__ arrays; no allocation allowed)
__device__ float   g_ft [N_NODES_MAX * HD];   // projected features fp32 [N,128]
__device__ __half2 g_fth[N_NODES_MAX * 64];   // same rows as half2 (gather mirror)
__device__ int     g_cnt[N_NODES_MAX];        // in-degree histogram
__device__ int     g_off[N_NODES_MAX];        // CSR row starts
__device__ int     g_cur[N_NODES_MAX];        // scatter cursors
__device__ int     g_bsum[MAX_BLOCKS];        // per-block sums for scan
__device__ int     g_csr_src[N_EDGES_MAX];    // src node per CSR slot

// ---------------------------------------------------------------------------
// K1: in-degree histogram
// ---------------------------------------------------------------------------
__global__ void hist_kernel(const int* __restrict__ dst, int E) {
    int i = blockIdx.x * blockDim.x + threadIdx.x;
    if (i < E) atomicAdd(&g_cnt[dst[i]], 1);
}

// ---------------------------------------------------------------------------
// K2a: per-block sums for the scan
// ---------------------------------------------------------------------------
__global__ void scan_phase1(int N) {
    int i = blockIdx.x * SCAN_B + threadIdx.x;
    int v = (i < N) ? g_cnt[i] : 0;
    #pragma unroll
    for (int o = 16; o > 0; o >>= 1) v += __shfl_xor_sync(0xffffffffu, v, o);
    __shared__ int wsum[32];
    int lane = threadIdx.x & 31, w = threadIdx.x >> 5;
    if (lane == 0) wsum[w] = v;
    __syncthreads();
    if (w == 0) {
        int x = wsum[lane];
        #pragma unroll
        for (int o = 16; o > 0; o >>= 1) x += __shfl_xor_sync(0xffffffffu, x, o);
        if (lane == 0) g_bsum[blockIdx.x] = x;
    }
}

// ---------------------------------------------------------------------------
// K2b: per-block scan with inter-block base folded in (warp 0 sums g_bsum).
// ---------------------------------------------------------------------------
__global__ void scan_phase3(int N) {
    __shared__ int base_off;
    int lane = threadIdx.x & 31, w = threadIdx.x >> 5;
    if (threadIdx.x < 32) {
        int acc = 0;
        for (int j = lane; j < (int)blockIdx.x; j += 32) acc += g_bsum[j];
        #pragma unroll
        for (int o = 16; o > 0; o >>= 1) acc += __shfl_xor_sync(0xffffffffu, acc, o);
        if (lane == 0) base_off = acc;
    }
    int i = blockIdx.x * SCAN_B + threadIdx.x;
    int v = (i < N) ? g_cnt[i] : 0;
    int x = v;
    #pragma unroll
    for (int o = 1; o < 32; o <<= 1) {
        int y = __shfl_up_sync(0xffffffffu, x, o);
        if (lane >= o) x += y;
    }
    __shared__ int woff[32];
    if (lane == 31) woff[w] = x;
    __syncthreads();
    if (w == 0) {
        int y = woff[lane];
        int z = y;
        #pragma unroll
        for (int o = 1; o < 32; o <<= 1) {
            int t2 = __shfl_up_sync(0xffffffffu, z, o);
            if (lane >= o) z += t2;
        }
        woff[lane] = z - y;
    }
    __syncthreads();
    int excl = (x - v) + woff[w] + base_off;
    if (i < N) { g_off[i] = excl; g_cur[i] = excl; }
}

// ---------------------------------------------------------------------------
// K3: scatter src ids into CSR slots
// ---------------------------------------------------------------------------
__global__ void scatter_kernel(const int* __restrict__ src,
                               const int* __restrict__ dst, int E) {
    int i = blockIdx.x * blockDim.x + threadIdx.x;
    if (i < E) {
        int pos = atomicAdd(&g_cur[dst[i]], 1);
        g_csr_src[pos] = src[i];
    }
}

// ---------------------------------------------------------------------------
// K4: projection GEMM — R8 exact shape (measured best; do not reshape).
// 128x128 tile, BK=16, 256 threads, occ 2, 8x8 microtile as f32x2 pairs.
// Epilogue ADDITION: also emit fp16 mirror rows (g_fth) for the agg gather.
// Runs on a forked stream, concurrent with the CSR build.
// ---------------------------------------------------------------------------
#define GM 128
#define GK 16
__global__ void __launch_bounds__(256, 2)
gemm_kernel(const float* __restrict__ feat,
            const float* __restrict__ W,
            int N) {
    __shared__ float As[GK][GM];    // feat tile, transposed: As[k][r]   8KB
    __shared__ float Bs[GK][HD];    // W tile, transposed:    Bs[k][o]   8KB

    const int tid = threadIdx.x;           // 0..255
    const int tx  = tid & 15;              // col group: cols tx*8..tx*8+7
    const int ty  = tid >> 4;              // row group: rows ty*8..ty*8+7
    const int row0 = blockIdx.x * GM;

    const int rA0 = (tid + 0)   >> 2, kq0 = (tid + 0)   & 3;
    const int rA1 = (tid + 256) >> 2, kq1 = (tid + 256) & 3;

    unsigned long long acc[8][4];   // 8 rows x 4 f32x2 pairs (= 8 cols)
    #pragma unroll
    for (int i = 0; i < 8; i++)
        #pragma unroll
        for (int j = 0; j < 4; j++) acc[i][j] = 0ULL;

    // Prologue: stage k-block 0 into registers
    float4 fa0, fa1, fw0, fw1;
    {
        fa0 = make_float4(0.f, 0.f, 0.f, 0.f);
        fa1 = fa0;
        if (row0 + rA0 < N) fa0 = *(const float4*)&feat[(size_t)(row0 + rA0) * IN_FEATS + (kq0 << 2)];
        if (row0 + rA1 < N) fa1 = *(const float4*)&feat[(size_t)(row0 + rA1) * IN_FEATS + (kq1 << 2)];
        fw0 = *(const float4*)&W[(size_t)rA0 * IN_FEATS + (kq0 << 2)];
        fw1 = *(const float4*)&W[(size_t)rA1 * IN_FEATS + (kq1 << 2)];
    }

    #pragma unroll 1
    for (int kb = 0; kb < IN_FEATS / GK; kb++) {
        As[(kq0 << 2) + 0][rA0] = fa0.x; As[(kq0 << 2) + 1][rA0] = fa0.y;
        As[(kq0 << 2) + 2][rA0] = fa0.z; As[(kq0 << 2) + 3][rA0] = fa0.w;
        As[(kq1 << 2) + 0][rA1] = fa1.x; As[(kq1 << 2) + 1][rA1] = fa1.y;
        As[(kq1 << 2) + 2][rA1] = fa1.z; As[(kq1 << 2) + 3][rA1] = fa1.w;
        Bs[(kq0 << 2) + 0][rA0] = fw0.x; Bs[(kq0 << 2) + 1][rA0] = fw0.y;
        Bs[(kq0 << 2) + 2][rA0] = fw0.z; Bs[(kq0 << 2) + 3][rA0] = fw0.w;
        Bs[(kq1 << 2) + 0][rA1] = fw1.x; Bs[(kq1 << 2) + 1][rA1] = fw1.y;
        Bs[(kq1 << 2) + 2][rA1] = fw1.z; Bs[(kq1 << 2) + 3][rA1] = fw1.w;
        __syncthreads();

        if (kb + 1 < IN_FEATS / GK) {
            int kc = (kb + 1) * GK;
            fa0 = make_float4(0.f, 0.f, 0.f, 0.f);
            fa1 = fa0;
            if (row0 + rA0 < N) fa0 = *(const float4*)&feat[(size_t)(row0 + rA0) * IN_FEATS + kc + (kq0 << 2)];
            if (row0 + rA1 < N) fa1 = *(const float4*)&feat[(size_t)(row0 + rA1) * IN_FEATS + kc + (kq1 << 2)];
            fw0 = *(const float4*)&W[(size_t)rA0 * IN_FEATS + kc + (kq0 << 2)];
            fw1 = *(const float4*)&W[(size_t)rA1 * IN_FEATS + kc + (kq1 << 2)];
        }

        #pragma unroll
        for (int k = 0; k < GK; k++) {
            float4 a0 = *(const float4*)&As[k][(ty << 3) + 0];
            float4 a1 = *(const float4*)&As[k][(ty << 3) + 4];
            float4 b0 = *(const float4*)&Bs[k][(tx << 3) + 0];
            float4 b1 = *(const float4*)&Bs[k][(tx << 3) + 4];
            unsigned long long bp[4];
            asm("mov.b64 %0, {%1, %2};" : "=l"(bp[0]) : "f"(b0.x), "f"(b0.y));
            asm("mov.b64 %0, {%1, %2};" : "=l"(bp[1]) : "f"(b0.z), "f"(b0.w));
            asm("mov.b64 %0, {%1, %2};" : "=l"(bp[2]) : "f"(b1.x), "f"(b1.y));
            asm("mov.b64 %0, {%1, %2};" : "=l"(bp[3]) : "f"(b1.z), "f"(b1.w));
            float av[8] = {a0.x, a0.y, a0.z, a0.w, a1.x, a1.y, a1.z, a1.w};
            #pragma unroll
            for (int i = 0; i < 8; i++) {
                unsigned long long ap;
                asm("mov.b64 %0, {%1, %1};" : "=l"(ap) : "f"(av[i]));
                #pragma unroll
                for (int jp = 0; jp < 4; jp++)
                    asm("fma.rn.f32x2 %0, %1, %2, %0;"
                        : "+l"(acc[i][jp]) : "l"(ap), "l"(bp[jp]));
            }
        }
        __syncthreads();
    }

    // Epilogue: fp32 rows (two STG.128) + fp16 mirror row chunk (one STG.128).
    #pragma unroll
    for (int i = 0; i < 8; i++) {
        int r = row0 + (ty << 3) + i;
        if (r < N) {
            unsigned long long* d =
                (unsigned long long*)&g_ft[(size_t)r * HD + (tx << 3)];
            ulonglong2 v0; v0.x = acc[i][0]; v0.y = acc[i][1];
            ulonglong2 v1; v1.x = acc[i][2]; v1.y = acc[i][3];
            *(ulonglong2*)(d + 0) = v0;
            *(ulonglong2*)(d + 2) = v1;

            __half2 hh[4];
            #pragma unroll
            for (int jp = 0; jp < 4; jp++) {
                float2 f = *reinterpret_cast<float2*>(&acc[i][jp]);
                hh[jp] = __floats2half2_rn(f.x, f.y);
            }
            *(uint2*)&g_fth[(size_t)r * 64 + (tx << 2) + 0] = *(uint2*)&hh[0];
            *(uint2*)&g_fth[(size_t)r * 64 + (tx << 2) + 2] = *(uint2*)&hh[2];
        }
    }
}

// ---------------------------------------------------------------------------
// K5: atomic-free aggregation — R8 structure (depth-1 pipeline, unroll 2),
// with the per-edge gather switched to the fp16 mirror: 8 B/lane = 256 B/warp
// per edge (half the L2 lines/sectors of the fp32 gather). ft[dst] stays
// fp32 (loaded once per node). All arithmetic fp32.
// Max-subtraction skipped: mathematically identical softmax; |p*scale| <~ 7.
// ---------------------------------------------------------------------------
__global__ void agg_kernel(float* __restrict__ out, int N) {
    const int node = (blockIdx.x * blockDim.x + threadIdx.x) >> 5;
    if (node >= N) return;
    const int lane = threadIdx.x & 31;

    const int start = g_off[node];
    const int deg   = g_cnt[node];

    const float4* ft4 = (const float4*)g_ft;
    const float4 b4 = ft4[(size_t)node * 32 + lane];   // dst row, fp32

    float4 acc = make_float4(0.f, 0.f, 0.f, 0.f);
    float s = 0.0f;
    const float scale = 0.17677669529663687f;  // 1/sqrt(32)

    for (int base = 0; base < deg; base += 32) {
        int j = base + lane;
        int sj = (j < deg) ? g_csr_src[start + j] : 0;
        int cnt = min(32, deg - base);

        // depth-1 pipeline on the raw fp16 payload (8B per lane)
        int sn0 = __shfl_sync(0xffffffffu, sj, 0);
        uint2 raw = *(const uint2*)&g_fth[(size_t)sn0 * 64 + (lane << 1)];

        #pragma unroll 2
        for (int t = 0; t < cnt; t++) {
            uint2 rcur = raw;
            if (t + 1 < cnt) {   // prefetch next edge's row chunk
                int sn = __shfl_sync(0xffffffffu, sj, t + 1);
                raw = *(const uint2*)&g_fth[(size_t)sn * 64 + (lane << 1)];
            }
            float2 f0 = __half22float2(*reinterpret_cast<__half2*>(&rcur.x));
            float2 f1 = __half22float2(*reinterpret_cast<__half2*>(&rcur.y));
            float p = f0.x * b4.x + f0.y * b4.y + f1.x * b4.z + f1.y * b4.w;
            p += __shfl_xor_sync(0xffffffffu, p, 4);
            p += __shfl_xor_sync(0xffffffffu, p, 2);
            p += __shfl_xor_sync(0xffffffffu, p, 1);
            float e = __expf(p * scale);
            s += e;
            acc.x += e * f0.x; acc.y += e * f0.y;
            acc.z += e * f1.x; acc.w += e * f1.y;
        }
    }

    float inv = (deg > 0) ? (1.0f / s) : 0.0f;
    float4 r = make_float4(acc.x * inv, acc.y * inv, acc.z * inv, acc.w * inv);
    ((float4*)out)[(size_t)node * 32 + lane] = r;
}

// ---------------------------------------------------------------------------
extern "C" void kernel_launch(void* const* d_in, const int* in_sizes, int n_in,
                              void* d_out, int out_size) {
    const float* feat = (const float*)d_in[0];
    const float* W    = (const float*)d_in[1];
    const int*   src  = (const int*)d_in[2];
    const int*   dst  = (const int*)d_in[3];
    float* out = (float*)d_out;

    const int N = in_sizes[0] / IN_FEATS;   // 50000
    const int E = in_sizes[2];              // 800000
    const int nb = (N + SCAN_B - 1) / SCAN_B;

    // One-time resources (stream/events/symbol addr) — resources only;
    // the captured work per call is identical every time.
    static cudaStream_t s_gemm = nullptr;
    static cudaEvent_t  ev_fork = nullptr, ev_join = nullptr;
    static int* cnt_ptr = nullptr;
    if (s_gemm == nullptr) {
        cudaStreamCreateWithFlags(&s_gemm, cudaStreamNonBlocking);
        cudaEventCreateWithFlags(&ev_fork, cudaEventDisableTiming);
        cudaEventCreateWithFlags(&ev_join, cudaEventDisableTiming);
        cudaGetSymbolAddress((void**)&cnt_ptr, g_cnt);
    }

    // ---- fork: GEMM branch issued FIRST (R8 order — measured best) ----
    cudaEventRecord(ev_fork, 0);
    cudaStreamWaitEvent(s_gemm, ev_fork, 0);
    gemm_kernel<<<(N + GM - 1) / GM, 256, 0, s_gemm>>>(feat, W, N);
    cudaEventRecord(ev_join, s_gemm);

    // ---- main stream: CSR build branch (depends only on src, dst) ----
    cudaMemsetAsync(cnt_ptr, 0, (size_t)N * sizeof(int));
    hist_kernel<<<(E + 255) / 256, 256>>>(dst, E);
    scan_phase1<<<nb, SCAN_B>>>(N);
    scan_phase3<<<nb, SCAN_B>>>(N);
    scatter_kernel<<<(E + 255) / 256, 256>>>(src, dst, E);

    // ---- join, then aggregate ----
    cudaStreamWaitEvent(0, ev_join, 0);
    {
        int warps_per_block = 8;  // 256 threads
        int blocks = (N + warps_per_block - 1) / warps_per_block;
        agg_kernel<<<blocks, 256>>>(out, N);
    }
}

// round 14
// speedup vs baseline: 2.0418x; 1.0570x over previous
#include <cuda_runtime.h>
#include <cuda_fp16.h>
#include <cuda_bf16.h>
#include <cstdint>

// Problem constants (fixed by the dataset)
#define N_NODES_MAX 50048
#define N_EDGES_MAX 800000
#define IN_FEATS    128
#define NUM_HEADS   4
#define OUT_FEATS   32
#define HD          (NUM_HEADS * OUT_FEATS)   // 128

#define SCAN_B 1024
#define MAX_BLOCKS ((N_NODES_MAX + SCAN_B - 1) / SCAN_B + 2)

// Scratch (static __device__ arrays; no allocation allowed)
__device__ float   g_ft [N_NODES_MAX * HD];   // projected features fp32 [N,128]
__device__ __half2 g_fth[N_NODES_MAX * 64];   // same rows as half2 (gather mirror)
__device__ int     g_cnt[N_NODES_MAX];        // in-degree histogram
__device__ int     g_off[N_NODES_MAX];        // CSR row starts
__device__ int     g_cur[N_NODES_MAX];        // scatter cursors
__device__ int     g_bsum[MAX_BLOCKS];        // per-block sums for scan
__device__ int     g_csr_src[N_EDGES_MAX];    // src node per CSR slot

// ---------------------------------------------------------------------------
// K1: in-degree histogram
// ---------------------------------------------------------------------------
__global__ void hist_kernel(const int* __restrict__ dst, int E) {
    int i = blockIdx.x * blockDim.x + threadIdx.x;
    if (i < E) atomicAdd(&g_cnt[dst[i]], 1);
}

// ---------------------------------------------------------------------------
// K2a: per-block sums for the scan
// ---------------------------------------------------------------------------
__global__ void scan_phase1(int N) {
    int i = blockIdx.x * SCAN_B + threadIdx.x;
    int v = (i < N) ? g_cnt[i] : 0;
    #pragma unroll
    for (int o = 16; o > 0; o >>= 1) v += __shfl_xor_sync(0xffffffffu, v, o);
    __shared__ int wsum[32];
    int lane = threadIdx.x & 31, w = threadIdx.x >> 5;
    if (lane == 0) wsum[w] = v;
    __syncthreads();
    if (w == 0) {
        int x = wsum[lane];
        #pragma unroll
        for (int o = 16; o > 0; o >>= 1) x += __shfl_xor_sync(0xffffffffu, x, o);
        if (lane == 0) g_bsum[blockIdx.x] = x;
    }
}

// ---------------------------------------------------------------------------
// K2b: per-block scan with inter-block base folded in (warp 0 sums g_bsum).
// ---------------------------------------------------------------------------
__global__ void scan_phase3(int N) {
    __shared__ int base_off;
    int lane = threadIdx.x & 31, w = threadIdx.x >> 5;
    if (threadIdx.x < 32) {
        int acc = 0;
        for (int j = lane; j < (int)blockIdx.x; j += 32) acc += g_bsum[j];
        #pragma unroll
        for (int o = 16; o > 0; o >>= 1) acc += __shfl_xor_sync(0xffffffffu, acc, o);
        if (lane == 0) base_off = acc;
    }
    int i = blockIdx.x * SCAN_B + threadIdx.x;
    int v = (i < N) ? g_cnt[i] : 0;
    int x = v;
    #pragma unroll
    for (int o = 1; o < 32; o <<= 1) {
        int y = __shfl_up_sync(0xffffffffu, x, o);
        if (lane >= o) x += y;
    }
    __shared__ int woff[32];
    if (lane == 31) woff[w] = x;
    __syncthreads();
    if (w == 0) {
        int y = woff[lane];
        int z = y;
        #pragma unroll
        for (int o = 1; o < 32; o <<= 1) {
            int t2 = __shfl_up_sync(0xffffffffu, z, o);
            if (lane >= o) z += t2;
        }
        woff[lane] = z - y;
    }
    __syncthreads();
    int excl = (x - v) + woff[w] + base_off;
    if (i < N) { g_off[i] = excl; g_cur[i] = excl; }
}

// ---------------------------------------------------------------------------
// K3: scatter src ids into CSR slots
// ---------------------------------------------------------------------------
__global__ void scatter_kernel(const int* __restrict__ src,
                               const int* __restrict__ dst, int E) {
    int i = blockIdx.x * blockDim.x + threadIdx.x;
    if (i < E) {
        int pos = atomicAdd(&g_cur[dst[i]], 1);
        g_csr_src[pos] = src[i];
    }
}

// ---------------------------------------------------------------------------
// K4: projection GEMM — R8 exact shape (measured best; do not reshape).
// 128x128 tile, BK=16, 256 threads, occ 2, 8x8 microtile as f32x2 pairs.
// Epilogue also emits fp16 mirror rows (g_fth) for the agg gather.
// Runs on a forked stream, concurrent with the CSR build.
// ---------------------------------------------------------------------------
#define GM 128
#define GK 16
__global__ void __launch_bounds__(256, 2)
gemm_kernel(const float* __restrict__ feat,
            const float* __restrict__ W,
            int N) {
    __shared__ float As[GK][GM];    // feat tile, transposed: As[k][r]   8KB
    __shared__ float Bs[GK][HD];    // W tile, transposed:    Bs[k][o]   8KB

    const int tid = threadIdx.x;           // 0..255
    const int tx  = tid & 15;              // col group: cols tx*8..tx*8+7
    const int ty  = tid >> 4;              // row group: rows ty*8..ty*8+7
    const int row0 = blockIdx.x * GM;

    const int rA0 = (tid + 0)   >> 2, kq0 = (tid + 0)   & 3;
    const int rA1 = (tid + 256) >> 2, kq1 = (tid + 256) & 3;

    unsigned long long acc[8][4];   // 8 rows x 4 f32x2 pairs (= 8 cols)
    #pragma unroll
    for (int i = 0; i < 8; i++)
        #pragma unroll
        for (int j = 0; j < 4; j++) acc[i][j] = 0ULL;

    float4 fa0, fa1, fw0, fw1;
    {
        fa0 = make_float4(0.f, 0.f, 0.f, 0.f);
        fa1 = fa0;
        if (row0 + rA0 < N) fa0 = *(const float4*)&feat[(size_t)(row0 + rA0) * IN_FEATS + (kq0 << 2)];
        if (row0 + rA1 < N) fa1 = *(const float4*)&feat[(size_t)(row0 + rA1) * IN_FEATS + (kq1 << 2)];
        fw0 = *(const float4*)&W[(size_t)rA0 * IN_FEATS + (kq0 << 2)];
        fw1 = *(const float4*)&W[(size_t)rA1 * IN_FEATS + (kq1 << 2)];
    }

    #pragma unroll 1
    for (int kb = 0; kb < IN_FEATS / GK; kb++) {
        As[(kq0 << 2) + 0][rA0] = fa0.x; As[(kq0 << 2) + 1][rA0] = fa0.y;
        As[(kq0 << 2) + 2][rA0] = fa0.z; As[(kq0 << 2) + 3][rA0] = fa0.w;
        As[(kq1 << 2) + 0][rA1] = fa1.x; As[(kq1 << 2) + 1][rA1] = fa1.y;
        As[(kq1 << 2) + 2][rA1] = fa1.z; As[(kq1 << 2) + 3][rA1] = fa1.w;
        Bs[(kq0 << 2) + 0][rA0] = fw0.x; Bs[(kq0 << 2) + 1][rA0] = fw0.y;
        Bs[(kq0 << 2) + 2][rA0] = fw0.z; Bs[(kq0 << 2) + 3][rA0] = fw0.w;
        Bs[(kq1 << 2) + 0][rA1] = fw1.x; Bs[(kq1 << 2) + 1][rA1] = fw1.y;
        Bs[(kq1 << 2) + 2][rA1] = fw1.z; Bs[(kq1 << 2) + 3][rA1] = fw1.w;
        __syncthreads();

        if (kb + 1 < IN_FEATS / GK) {
            int kc = (kb + 1) * GK;
            fa0 = make_float4(0.f, 0.f, 0.f, 0.f);
            fa1 = fa0;
            if (row0 + rA0 < N) fa0 = *(const float4*)&feat[(size_t)(row0 + rA0) * IN_FEATS + kc + (kq0 << 2)];
            if (row0 + rA1 < N) fa1 = *(const float4*)&feat[(size_t)(row0 + rA1) * IN_FEATS + kc + (kq1 << 2)];
            fw0 = *(const float4*)&W[(size_t)rA0 * IN_FEATS + kc + (kq0 << 2)];
            fw1 = *(const float4*)&W[(size_t)rA1 * IN_FEATS + kc + (kq1 << 2)];
        }

        #pragma unroll
        for (int k = 0; k < GK; k++) {
            float4 a0 = *(const float4*)&As[k][(ty << 3) + 0];
            float4 a1 = *(const float4*)&As[k][(ty << 3) + 4];
            float4 b0 = *(const float4*)&Bs[k][(tx << 3) + 0];
            float4 b1 = *(const float4*)&Bs[k][(tx << 3) + 4];
            unsigned long long bp[4];
            asm("mov.b64 %0, {%1, %2};" : "=l"(bp[0]) : "f"(b0.x), "f"(b0.y));
            asm("mov.b64 %0, {%1, %2};" : "=l"(bp[1]) : "f"(b0.z), "f"(b0.w));
            asm("mov.b64 %0, {%1, %2};" : "=l"(bp[2]) : "f"(b1.x), "f"(b1.y));
            asm("mov.b64 %0, {%1, %2};" : "=l"(bp[3]) : "f"(b1.z), "f"(b1.w));
            float av[8] = {a0.x, a0.y, a0.z, a0.w, a1.x, a1.y, a1.z, a1.w};
            #pragma unroll
            for (int i = 0; i < 8; i++) {
                unsigned long long ap;
                asm("mov.b64 %0, {%1, %1};" : "=l"(ap) : "f"(av[i]));
                #pragma unroll
                for (int jp = 0; jp < 4; jp++)
                    asm("fma.rn.f32x2 %0, %1, %2, %0;"
                        : "+l"(acc[i][jp]) : "l"(ap), "l"(bp[jp]));
            }
        }
        __syncthreads();
    }

    #pragma unroll
    for (int i = 0; i < 8; i++) {
        int r = row0 + (ty << 3) + i;
        if (r < N) {
            unsigned long long* d =
                (unsigned long long*)&g_ft[(size_t)r * HD + (tx << 3)];
            ulonglong2 v0; v0.x = acc[i][0]; v0.y = acc[i][1];
            ulonglong2 v1; v1.x = acc[i][2]; v1.y = acc[i][3];
            *(ulonglong2*)(d + 0) = v0;
            *(ulonglong2*)(d + 2) = v1;

            __half2 hh[4];
            #pragma unroll
            for (int jp = 0; jp < 4; jp++) {
                float2 f = *reinterpret_cast<float2*>(&acc[i][jp]);
                hh[jp] = __floats2half2_rn(f.x, f.y);
            }
            *(uint2*)&g_fth[(size_t)r * 64 + (tx << 2) + 0] = *(uint2*)&hh[0];
            *(uint2*)&g_fth[(size_t)r * 64 + (tx << 2) + 2] = *(uint2*)&hh[2];
        }
    }
}

// ---------------------------------------------------------------------------
// K5: atomic-free aggregation — HALF-WARP PER EDGE.
// fp16 rows are 256B = 16 lanes x uint4, so one warp processes 2 edges per
// iteration: lanes 0-15 take edge t, lanes 16-31 take edge t+1. Each lane
// holds 8 features (8*(lane&15)..+7), whose head is (lane&15)/4, so the
// per-head dot reduction is only 2 shuffles (within a lane quad) instead
// of 3 — shorter chain AND 2-edge ILP per warp. s and acc are merged across
// half-warps once per node with xor-16 shuffles.
// Max-subtraction skipped: mathematically identical softmax; |p*scale| <~ 7.
// ---------------------------------------------------------------------------
__global__ void agg_kernel(float* __restrict__ out, int N) {
    const int node = (blockIdx.x * blockDim.x + threadIdx.x) >> 5;
    if (node >= N) return;
    const int lane  = threadIdx.x & 31;
    const int hl    = lane & 15;      // position within half-warp
    const int eslot = lane >> 4;      // 0: even edges, 1: odd edges

    const int start = g_off[node];
    const int deg   = g_cnt[node];

    // dst row chunk: features 8*hl .. 8*hl+7, fp32
    float b[8];
    {
        float4 b0 = *(const float4*)&g_ft[(size_t)node * HD + (hl << 3) + 0];
        float4 b1 = *(const float4*)&g_ft[(size_t)node * HD + (hl << 3) + 4];
        b[0] = b0.x; b[1] = b0.y; b[2] = b0.z; b[3] = b0.w;
        b[4] = b1.x; b[5] = b1.y; b[6] = b1.z; b[7] = b1.w;
    }

    float acc[8];
    #pragma unroll
    for (int i = 0; i < 8; i++) acc[i] = 0.0f;
    float s = 0.0f;
    const float scale = 0.17677669529663687f;  // 1/sqrt(32)

    const uint4* fth4 = (const uint4*)g_fth;   // 16 uint4 per row

    for (int base = 0; base < deg; base += 32) {
        int j = base + lane;
        int sj = (j < deg) ? g_csr_src[start + j] : 0;
        int cnt = min(32, deg - base);

        // prologue: this half-warp's first edge (t=0 -> edge eslot)
        int my = eslot;
        int sn = __shfl_sync(0xffffffffu, sj, min(my, 31));
        uint4 raw = fth4[(size_t)sn * 16 + hl];

        #pragma unroll 1
        for (int t = 0; t < cnt; t += 2) {
            uint4 cur = raw;
            bool valid = (t + eslot) < cnt;

            // prefetch next pair's edge (uniform-shape shuffle, clamped idx)
            int nxt = t + 2 + eslot;
            int snn = __shfl_sync(0xffffffffu, sj, min(nxt, 31));
            if (nxt < cnt) raw = fth4[(size_t)snn * 16 + hl];

            // convert 8 halves -> 8 floats, dot with dst chunk
            float2 f0 = __half22float2(*reinterpret_cast<__half2*>(&cur.x));
            float2 f1 = __half22float2(*reinterpret_cast<__half2*>(&cur.y));
            float2 f2 = __half22float2(*reinterpret_cast<__half2*>(&cur.z));
            float2 f3 = __half22float2(*reinterpret_cast<__half2*>(&cur.w));
            float p = f0.x * b[0] + f0.y * b[1] + f1.x * b[2] + f1.y * b[3]
                    + f2.x * b[4] + f2.y * b[5] + f3.x * b[6] + f3.y * b[7];
            // reduce over the 4 lanes of this head quad
            p += __shfl_xor_sync(0xffffffffu, p, 1);
            p += __shfl_xor_sync(0xffffffffu, p, 2);

            float e = valid ? __expf(p * scale) : 0.0f;
            s += e;
            acc[0] += e * f0.x; acc[1] += e * f0.y;
            acc[2] += e * f1.x; acc[3] += e * f1.y;
            acc[4] += e * f2.x; acc[5] += e * f2.y;
            acc[6] += e * f3.x; acc[7] += e * f3.y;
        }
    }

    // merge the two half-warps (same features, disjoint edge subsets)
    #pragma unroll
    for (int i = 0; i < 8; i++)
        acc[i] += __shfl_xor_sync(0xffffffffu, acc[i], 16);
    s += __shfl_xor_sync(0xffffffffu, s, 16);

    float inv = (deg > 0) ? (1.0f / s) : 0.0f;
    // lanes 0-15 write first float4 of their chunk, lanes 16-31 the second:
    // one fully-coalesced 512B row store.
    float4 v;
    if (eslot == 0) v = make_float4(acc[0] * inv, acc[1] * inv, acc[2] * inv, acc[3] * inv);
    else            v = make_float4(acc[4] * inv, acc[5] * inv, acc[6] * inv, acc[7] * inv);
    *(float4*)&out[(size_t)node * HD + (hl << 3) + (eslot << 2)] = v;
}

// ---------------------------------------------------------------------------
extern "C" void kernel_launch(void* const* d_in, const int* in_sizes, int n_in,
                              void* d_out, int out_size) {
    const float* feat = (const float*)d_in[0];
    const float* W    = (const float*)d_in[1];
    const int*   src  = (const int*)d_in[2];
    const int*   dst  = (const int*)d_in[3];
    float* out = (float*)d_out;

    const int N = in_sizes[0] / IN_FEATS;   // 50000
    const int E = in_sizes[2];              // 800000
    const int nb = (N + SCAN_B - 1) / SCAN_B;

    static cudaStream_t s_gemm = nullptr;
    static cudaEvent_t  ev_fork = nullptr, ev_join = nullptr;
    static int* cnt_ptr = nullptr;
    if (s_gemm == nullptr) {
        cudaStreamCreateWithFlags(&s_gemm, cudaStreamNonBlocking);
        cudaEventCreateWithFlags(&ev_fork, cudaEventDisableTiming);
        cudaEventCreateWithFlags(&ev_join, cudaEventDisableTiming);
        cudaGetSymbolAddress((void**)&cnt_ptr, g_cnt);
    }

    // ---- fork: GEMM branch issued FIRST (R8 order — measured best) ----
    cudaEventRecord(ev_fork, 0);
    cudaStreamWaitEvent(s_gemm, ev_fork, 0);
    gemm_kernel<<<(N + GM - 1) / GM, 256, 0, s_gemm>>>(feat, W, N);
    cudaEventRecord(ev_join, s_gemm);

    // ---- main stream: CSR build branch (depends only on src, dst) ----
    cudaMemsetAsync(cnt_ptr, 0, (size_t)N * sizeof(int));
    hist_kernel<<<(E + 255) / 256, 256>>>(dst, E);
    scan_phase1<<<nb, SCAN_B>>>(N);
    scan_phase3<<<nb, SCAN_B>>>(N);
    scatter_kernel<<<(E + 255) / 256, 256>>>(src, dst, E);

    // ---- join, then aggregate ----
    cudaStreamWaitEvent(0, ev_join, 0);
    {
        int warps_per_block = 8;  // 256 threads
        int blocks = (N + warps_per_block - 1) / warps_per_block;
        agg_kernel<<<blocks, 256>>>(out, N);
    }
}